// round 2
// baseline (speedup 1.0000x reference)
#include <cuda_runtime.h>

#define E 1024
#define R 16
#define BATCH 4
#define S 2048
#define BS (BATCH * S)           // 8192 rows total

// ---------------- device scratch (static; no runtime allocation) ----------------
__device__ float g_Weff[3][(size_t)E * E];                 // 12 MB
__device__ float g_QKV[3][(size_t)BATCH * S * E];          // 96 MB
__device__ float g_scores[(size_t)BATCH * S * S];          // 64 MB
__device__ float g_attnout[(size_t)BATCH * S * E];         // 32 MB

// Buffer selectors so kernel_launch contains ONLY kernel launches
// (no cudaGetSymbolAddress / runtime API during graph capture).
#define SEL_EXT   0
#define SEL_WEFF  1
#define SEL_QKV   2
#define SEL_SCORE 3
#define SEL_AOUT  4

__device__ __forceinline__ float* resolve_buf(int sel, const float* ext) {
    switch (sel) {
        case SEL_WEFF:  return &g_Weff[0][0];
        case SEL_QKV:   return &g_QKV[0][0];
        case SEL_SCORE: return &g_scores[0];
        case SEL_AOUT:  return &g_attnout[0];
        default:        return (float*)ext;
    }
}

// ---------------- packed f32x2 helpers (Blackwell dual fp32 pipe) ----------------
__device__ __forceinline__ unsigned long long pack2(float lo, float hi) {
    unsigned long long d;
    asm("mov.b64 %0, {%1, %2};" : "=l"(d) : "f"(lo), "f"(hi));
    return d;
}
__device__ __forceinline__ float2 unpack2(unsigned long long v) {
    float lo, hi;
    asm("mov.b64 {%0, %1}, %2;" : "=f"(lo), "=f"(hi) : "l"(v));
    return make_float2(lo, hi);
}
__device__ __forceinline__ unsigned long long fma2(unsigned long long a,
                                                   unsigned long long b,
                                                   unsigned long long c) {
    unsigned long long d;
    asm("fma.rn.f32x2 %0, %1, %2, %3;" : "=l"(d) : "l"(a), "l"(b), "l"(c));
    return d;
}

// ---------------- W_eff = W + B @ A  (fold LoRA into the dense weight) ----------------
__global__ __launch_bounds__(256) void weff_kernel(
    const float* __restrict__ Wq, const float* __restrict__ Wk, const float* __restrict__ Wv,
    const float* __restrict__ Aq, const float* __restrict__ Bq,
    const float* __restrict__ Ak, const float* __restrict__ Bk,
    const float* __restrict__ Av, const float* __restrict__ Bv)
{
    const int z = blockIdx.z;
    const float* W  = (z == 0) ? Wq : (z == 1) ? Wk : Wv;
    const float* Am = (z == 0) ? Aq : (z == 1) ? Ak : Av;
    const float* Bm = (z == 0) ? Bq : (z == 1) ? Bk : Bv;
    const int idx = blockIdx.x * 256 + threadIdx.x;   // f * E + e
    const int f = idx >> 10;
    const int e = idx & 1023;
    float sum = W[idx];
#pragma unroll
    for (int r = 0; r < R; r++)
        sum += Bm[f * R + r] * Am[r * E + e];
    g_Weff[z][idx] = sum;
}

// ---------------- tiled SGEMM, 128x128x16, 256 threads, 8x8 microtile, f32x2 FMA ---
// BT = true : C[M,N] = alpha * A[M,K] @ B[N,K]^T   (both row-major, "NT")
// BT = false: C[M,N] = alpha * A[M,K] @ B[K,N]     ("NN")
// blockIdx.z batches via strides sA/sB/sC.
// Buffers resolved from (sel, ext-pointer, element-offset) triples.
template <bool BT>
__global__ __launch_bounds__(256) void gemm_kernel(
    const float* extA, int selA, long long offA,
    const float* extB, int selB, long long offB,
    float* extC, int selC, long long offC,
    int M, int N, int K,
    long long sA, long long sB, long long sC, float alpha)
{
    const float* __restrict__ A = resolve_buf(selA, extA) + offA + (long long)blockIdx.z * sA;
    const float* __restrict__ B = resolve_buf(selB, extB) + offB + (long long)blockIdx.z * sB;
    float* __restrict__ C = resolve_buf(selC, extC) + offC + (long long)blockIdx.z * sC;

    __shared__ float As[16][132];   // stride 132 floats: 16B-aligned rows, <=2-way store conflict
    __shared__ float Bs[16][132];

    const int tid = threadIdx.x;
    const int tx = tid & 15;        // 0..15 -> 8 output cols each
    const int ty = tid >> 4;        // 0..15 -> 8 output rows each
    const int row0 = blockIdx.y * 128;
    const int col0 = blockIdx.x * 128;

    unsigned long long acc[8][4];
#pragma unroll
    for (int i = 0; i < 8; i++)
#pragma unroll
        for (int j = 0; j < 4; j++) acc[i][j] = 0ull;

    for (int k0 = 0; k0 < K; k0 += 16) {
        // ---- load A tile [128 x 16], stored transposed As[k][m]
#pragma unroll
        for (int l = 0; l < 2; l++) {
            const int f = tid + l * 256;          // 0..511 float4 slots
            const int m  = f >> 2;                // row within tile
            const int kk = (f & 3) << 2;          // k offset (0,4,8,12)
            const float4 v = *reinterpret_cast<const float4*>(
                A + (long long)(row0 + m) * K + (k0 + kk));
            As[kk + 0][m] = v.x; As[kk + 1][m] = v.y;
            As[kk + 2][m] = v.z; As[kk + 3][m] = v.w;
        }
        if (BT) {
            // B is [N,K]: same transpose-load as A
#pragma unroll
            for (int l = 0; l < 2; l++) {
                const int f = tid + l * 256;
                const int n  = f >> 2;
                const int kk = (f & 3) << 2;
                const float4 v = *reinterpret_cast<const float4*>(
                    B + (long long)(col0 + n) * K + (k0 + kk));
                Bs[kk + 0][n] = v.x; Bs[kk + 1][n] = v.y;
                Bs[kk + 2][n] = v.z; Bs[kk + 3][n] = v.w;
            }
        } else {
            // B is [K,N]: direct row copy
#pragma unroll
            for (int l = 0; l < 2; l++) {
                const int f = tid + l * 256;
                const int kk = f >> 5;                 // 0..15
                const int n4 = (f & 31) << 2;          // 0..124
                *reinterpret_cast<float4*>(&Bs[kk][n4]) =
                    *reinterpret_cast<const float4*>(
                        B + (long long)(k0 + kk) * N + (col0 + n4));
            }
        }
        __syncthreads();

#pragma unroll
        for (int kk = 0; kk < 16; kk++) {
            const float4 a0 = *reinterpret_cast<const float4*>(&As[kk][ty * 8]);
            const float4 a1 = *reinterpret_cast<const float4*>(&As[kk][ty * 8 + 4]);
            const float4 b0 = *reinterpret_cast<const float4*>(&Bs[kk][tx * 8]);
            const float4 b1 = *reinterpret_cast<const float4*>(&Bs[kk][tx * 8 + 4]);
            const unsigned long long bp[4] = {
                pack2(b0.x, b0.y), pack2(b0.z, b0.w),
                pack2(b1.x, b1.y), pack2(b1.z, b1.w)
            };
            const float av[8] = { a0.x, a0.y, a0.z, a0.w, a1.x, a1.y, a1.z, a1.w };
#pragma unroll
            for (int i = 0; i < 8; i++) {
                const unsigned long long ap = pack2(av[i], av[i]);
#pragma unroll
                for (int j = 0; j < 4; j++)
                    acc[i][j] = fma2(ap, bp[j], acc[i][j]);
            }
        }
        __syncthreads();
    }

    // ---- epilogue: scale + store as 2x float4 per row
#pragma unroll
    for (int i = 0; i < 8; i++) {
        const long long row = row0 + ty * 8 + i;
        float4 o0, o1;
        float2 p;
        p = unpack2(acc[i][0]); o0.x = p.x * alpha; o0.y = p.y * alpha;
        p = unpack2(acc[i][1]); o0.z = p.x * alpha; o0.w = p.y * alpha;
        p = unpack2(acc[i][2]); o1.x = p.x * alpha; o1.y = p.y * alpha;
        p = unpack2(acc[i][3]); o1.z = p.x * alpha; o1.w = p.y * alpha;
        *reinterpret_cast<float4*>(C + row * N + col0 + tx * 8)     = o0;
        *reinterpret_cast<float4*>(C + row * N + col0 + tx * 8 + 4) = o1;
    }
}

// ---------------- row softmax over S=2048, one block per row ----------------
__global__ __launch_bounds__(256) void softmax_kernel()
{
    const long long row = blockIdx.x;
    float* p = &g_scores[0] + row * (long long)S;
    const int t = threadIdx.x;

    float v[8];
    float m = -1e30f;
#pragma unroll
    for (int i = 0; i < 8; i++) {
        v[i] = p[t + i * 256];
        m = fmaxf(m, v[i]);
    }
    __shared__ float red[8];
#pragma unroll
    for (int o = 16; o; o >>= 1) m = fmaxf(m, __shfl_xor_sync(0xffffffffu, m, o));
    if ((t & 31) == 0) red[t >> 5] = m;
    __syncthreads();
    float mx = red[0];
#pragma unroll
    for (int w = 1; w < 8; w++) mx = fmaxf(mx, red[w]);

    float s = 0.f;
#pragma unroll
    for (int i = 0; i < 8; i++) {
        v[i] = __expf(v[i] - mx);
        s += v[i];
    }
#pragma unroll
    for (int o = 16; o; o >>= 1) s += __shfl_xor_sync(0xffffffffu, s, o);
    __syncthreads();                       // red[] reuse
    if ((t & 31) == 0) red[t >> 5] = s;
    __syncthreads();
    float tot = 0.f;
#pragma unroll
    for (int w = 0; w < 8; w++) tot += red[w];
    const float inv = 1.0f / tot;
#pragma unroll
    for (int i = 0; i < 8; i++) p[t + i * 256] = v[i] * inv;
}

// ---------------- launch (kernel launches ONLY — graph-capture safe) ----------------
extern "C" void kernel_launch(void* const* d_in, const int* in_sizes, int n_in,
                              void* d_out, int out_size)
{
    (void)in_sizes; (void)n_in; (void)out_size;
    const float* query = (const float*)d_in[0];
    const float* key   = (const float*)d_in[1];
    const float* value = (const float*)d_in[2];
    const float* Qw    = (const float*)d_in[3];
    const float* Kw    = (const float*)d_in[4];
    const float* Vw    = (const float*)d_in[5];
    const float* Qa    = (const float*)d_in[6];
    const float* Qb    = (const float*)d_in[7];
    const float* Ka    = (const float*)d_in[8];
    const float* Kb    = (const float*)d_in[9];
    const float* Va    = (const float*)d_in[10];
    const float* Vb    = (const float*)d_in[11];
    const float* Ow    = (const float*)d_in[12];
    float* out = (float*)d_out;

    const long long EE  = (long long)E * E;           // per-projection weight size
    const long long BSE = (long long)BATCH * S * E;   // per-projection activation size
    const long long SE  = (long long)S * E;           // per-batch Q/K/V stride
    const long long SS  = (long long)S * S;           // per-batch scores stride

    // 1. fold LoRA into weights: g_Weff[z] = W_z + B_z @ A_z
    weff_kernel<<<dim3(E * E / 256, 1, 3), 256>>>(Qw, Kw, Vw, Qa, Qb, Ka, Kb, Va, Vb);

    // 2. Q/K/V projections: [8192,1024] = X @ Weff^T
    const float* xs[3] = { query, key, value };
    for (int p = 0; p < 3; p++) {
        gemm_kernel<true><<<dim3(E / 128, BS / 128, 1), 256>>>(
            xs[p],   SEL_EXT,  0,
            nullptr, SEL_WEFF, p * EE,
            nullptr, SEL_QKV,  p * BSE,
            BS, E, E, 0, 0, 0, 1.0f);
    }

    // 3. scores = Q @ K^T / sqrt(E)   (batched over z)
    gemm_kernel<true><<<dim3(S / 128, S / 128, BATCH), 256>>>(
        nullptr, SEL_QKV,   0,          // Q
        nullptr, SEL_QKV,   BSE,        // K
        nullptr, SEL_SCORE, 0,
        S, S, E, SE, SE, SS, 1.0f / 32.0f);

    // 4. softmax rows
    softmax_kernel<<<BATCH * S, 256>>>();

    // 5. out = P @ V   (batched, NN)
    gemm_kernel<false><<<dim3(E / 128, S / 128, BATCH), 256>>>(
        nullptr, SEL_SCORE, 0,
        nullptr, SEL_QKV,   2 * BSE,    // V
        nullptr, SEL_AOUT,  0,
        S, E, S, SS, SE, SE, 1.0f);

    // 6. final = out @ O^T
    gemm_kernel<true><<<dim3(E / 128, BS / 128, 1), 256>>>(
        nullptr, SEL_AOUT, 0,
        Ow,      SEL_EXT,  0,
        out,     SEL_EXT,  0,
        BS, E, E, 0, 0, 0, 1.0f);
}

// round 4
// speedup vs baseline: 1.0416x; 1.0416x over previous
#include <cuda_runtime.h>
#include <cstdint>

#define E 1024
#define R 16
#define BATCH 4
#define S 2048
#define BS (BATCH * S)

// ---------------- device scratch ----------------
__device__ float g_Weff[3][(size_t)E * E];                 // 12 MB
__device__ float g_QKV[3][(size_t)BATCH * S * E];          // 96 MB
__device__ float g_Vt[(size_t)BATCH * S * E];              // 32 MB (V^T per batch: [E][S])
__device__ float g_scores[(size_t)BATCH * S * S];          // 64 MB
__device__ float g_attnout[(size_t)BATCH * S * E];         // 32 MB

#define SEL_EXT   0
#define SEL_WEFF  1
#define SEL_QKV   2
#define SEL_SCORE 3
#define SEL_AOUT  4
#define SEL_VT    5

__device__ __forceinline__ float* resolve_buf(int sel, const float* ext) {
    switch (sel) {
        case SEL_WEFF:  return &g_Weff[0][0];
        case SEL_QKV:   return &g_QKV[0][0];
        case SEL_SCORE: return &g_scores[0];
        case SEL_AOUT:  return &g_attnout[0];
        case SEL_VT:    return &g_Vt[0];
        default:        return (float*)ext;
    }
}

// ---------------- tf32 helpers ----------------
__device__ __forceinline__ uint32_t to_tf32(float x) {
    uint32_t r;
    asm("cvt.rna.tf32.f32 %0, %1;" : "=r"(r) : "f"(x));
    return r;
}

__device__ __forceinline__ void mma_tf32(float* c, const uint32_t* a, const uint32_t* b) {
    asm volatile("mma.sync.aligned.m16n8k8.row.col.f32.tf32.tf32.f32 "
        "{%0,%1,%2,%3}, {%4,%5,%6,%7}, {%8,%9}, {%0,%1,%2,%3};"
        : "+f"(c[0]), "+f"(c[1]), "+f"(c[2]), "+f"(c[3])
        : "r"(a[0]), "r"(a[1]), "r"(a[2]), "r"(a[3]), "r"(b[0]), "r"(b[1]));
}

// ---------------- W_eff = W + B @ A ----------------
__global__ __launch_bounds__(256) void weff_kernel(
    const float* __restrict__ Wq, const float* __restrict__ Wk, const float* __restrict__ Wv,
    const float* __restrict__ Aq, const float* __restrict__ Bq,
    const float* __restrict__ Ak, const float* __restrict__ Bk,
    const float* __restrict__ Av, const float* __restrict__ Bv)
{
    const int z = blockIdx.z;
    const float* W  = (z == 0) ? Wq : (z == 1) ? Wk : Wv;
    const float* Am = (z == 0) ? Aq : (z == 1) ? Ak : Av;
    const float* Bm = (z == 0) ? Bq : (z == 1) ? Bk : Bv;
    const int idx = blockIdx.x * 256 + threadIdx.x;
    const int f = idx >> 10;
    const int e = idx & 1023;
    float sum = W[idx];
#pragma unroll
    for (int r = 0; r < R; r++)
        sum += Bm[f * R + r] * Am[r * E + e];
    g_Weff[z][idx] = sum;
}

// ---------------- V transpose: Vt[b][e][s] = V[b][s][e] ----------------
__global__ __launch_bounds__(256) void transpose_v_kernel()
{
    __shared__ float t[32][33];
    const int b = blockIdx.z;
    const int s0 = blockIdx.x * 32;
    const int e0 = blockIdx.y * 32;
    const int tx = threadIdx.x & 31;
    const int ty = threadIdx.x >> 5;   // 0..7
    const float* V = &g_QKV[2][0] + (long long)b * S * E;
    float* Vt = &g_Vt[0] + (long long)b * S * E;
#pragma unroll
    for (int r = 0; r < 4; r++)
        t[ty + r * 8][tx] = V[(long long)(s0 + ty + r * 8) * E + e0 + tx];
    __syncthreads();
#pragma unroll
    for (int r = 0; r < 4; r++)
        Vt[(long long)(e0 + ty + r * 8) * S + s0 + tx] = t[tx][ty + r * 8];
}

// ---------------- split-TF32 HMMA GEMM ----------------
// C[M,N] = alpha * A[M,K] @ B[N,K]^T (all row-major), fp32-grade accuracy via
// 3-term split: A,B -> (hi, lo) tf32; acc += Ah*Bh + Al*Bh + Ah*Bl.
// CTA 128x128x32, 8 warps (2x4), warp tile 64x32 of m16n8k8 fragments.
// Smem holds tiles in MMA FRAGMENT ORDER so compute loads are LDS.128/LDS.64.
//
// Fragment-order layout per 32-float k8 chunk:
//  A: blocks fb = kc*8 + mtile (kc 0..3, mtile 0..7), 128 floats each:
//     idx = fb*128 + lane*4 + reg  (lane = (m%8)*4 + k%4, reg = ((m>>3)&1) + 2*((k>>2)&1))
//  B: blocks fb = kc*16 + ntile (ntile 0..15), 64 floats each:
//     idx = fb*64 + lane*2 + reg   (lane = (n%8)*4 + k%4, reg = (k>>2)&1)
// Planes (floats): aHi 0, aLo 4096, bHi 8192, bLo 12288; double buffer stride 16384.
#define GEMM_SMEM_BYTES (2 * 16384 * 4)

__global__ __launch_bounds__(256, 1) void gemm_hmma(
    const float* extA, int selA, long long offA, int ldA, long long sA,
    const float* extB, int selB, long long offB, int ldB, long long sB,
    float* extC, int selC, long long offC, int ldC, long long sC,
    int K, float alpha)
{
    extern __shared__ float smf[];
    const int tid = threadIdx.x;
    const int wid = tid >> 5, lane = tid & 31;
    const int g = lane >> 2, t4 = lane & 3;
    const int warp_m = wid & 1, warp_n = wid >> 1;

    const float* Ag = resolve_buf(selA, extA) + offA + (long long)blockIdx.z * sA
                      + (long long)blockIdx.y * 128 * ldA;
    const float* Bg = resolve_buf(selB, extB) + offB + (long long)blockIdx.z * sB
                      + (long long)blockIdx.x * 128 * ldB;
    float* Cg = resolve_buf(selC, extC) + offC + (long long)blockIdx.z * sC;

    float acc[4][4][4];
#pragma unroll
    for (int i = 0; i < 4; i++)
#pragma unroll
        for (int j = 0; j < 4; j++)
#pragma unroll
            for (int q = 0; q < 4; q++) acc[i][j][q] = 0.f;

    float4 va[4], vb[4];

    // global fetch of one 128x32 A tile + 128x32 B tile (float4 per thread x4)
    auto ldg = [&](int step) {
#pragma unroll
        for (int j = 0; j < 4; j++) {
            const int i = tid + j * 256;             // 0..1023
            const int row = i >> 3, q = i & 7;
            va[j] = *reinterpret_cast<const float4*>(Ag + (long long)row * ldA + step * 32 + q * 4);
            vb[j] = *reinterpret_cast<const float4*>(Bg + (long long)row * ldB + step * 32 + q * 4);
        }
    };

    // convert + scatter-store into fragment-order smem planes
    auto sts = [&](int s) {
        float* base = smf + s * 16384;
#pragma unroll
        for (int j = 0; j < 4; j++) {
            const int i = tid + j * 256;
            const int m = i >> 3, q = i & 7;
            const int kc = q >> 1, qodd = q & 1;
            // A
            {
                const int fb = kc * 8 + (m >> 4);
                const int regb = ((m >> 3) & 1) + 2 * qodd;
                const int lbase = (m & 7) * 4;
                const float vals[4] = { va[j].x, va[j].y, va[j].z, va[j].w };
#pragma unroll
                for (int jj = 0; jj < 4; jj++) {
                    const int idx = fb * 128 + (lbase + jj) * 4 + regb;
                    const uint32_t h = to_tf32(vals[jj]);
                    base[idx] = __uint_as_float(h);
                    base[4096 + idx] = __uint_as_float(to_tf32(vals[jj] - __uint_as_float(h)));
                }
            }
            // B
            {
                const int fb = kc * 16 + (m >> 3);
                const int lbase = (m & 7) * 4;
                const float vals[4] = { vb[j].x, vb[j].y, vb[j].z, vb[j].w };
#pragma unroll
                for (int jj = 0; jj < 4; jj++) {
                    const int idx = fb * 64 + (lbase + jj) * 2 + qodd;
                    const uint32_t h = to_tf32(vals[jj]);
                    base[8192 + idx] = __uint_as_float(h);
                    base[12288 + idx] = __uint_as_float(to_tf32(vals[jj] - __uint_as_float(h)));
                }
            }
        }
    };

    auto compute = [&](int s) {
        const float* base = smf + s * 16384;
#pragma unroll
        for (int kc = 0; kc < 4; kc++) {
            uint32_t aF[2][4][4], bF[2][4][2];
#pragma unroll
            for (int mt = 0; mt < 4; mt++) {
                const int fb = kc * 8 + warp_m * 4 + mt;
                const uint4 h = *reinterpret_cast<const uint4*>(base + fb * 128 + lane * 4);
                const uint4 l = *reinterpret_cast<const uint4*>(base + 4096 + fb * 128 + lane * 4);
                aF[0][mt][0] = h.x; aF[0][mt][1] = h.y; aF[0][mt][2] = h.z; aF[0][mt][3] = h.w;
                aF[1][mt][0] = l.x; aF[1][mt][1] = l.y; aF[1][mt][2] = l.z; aF[1][mt][3] = l.w;
            }
#pragma unroll
            for (int nt = 0; nt < 4; nt++) {
                const int fb = kc * 16 + warp_n * 4 + nt;
                const uint2 h = *reinterpret_cast<const uint2*>(base + 8192 + fb * 64 + lane * 2);
                const uint2 l = *reinterpret_cast<const uint2*>(base + 12288 + fb * 64 + lane * 2);
                bF[0][nt][0] = h.x; bF[0][nt][1] = h.y;
                bF[1][nt][0] = l.x; bF[1][nt][1] = l.y;
            }
#pragma unroll
            for (int mt = 0; mt < 4; mt++)
#pragma unroll
                for (int nt = 0; nt < 4; nt++)
                    mma_tf32(acc[mt][nt], aF[0][mt], bF[0][nt]);
#pragma unroll
            for (int mt = 0; mt < 4; mt++)
#pragma unroll
                for (int nt = 0; nt < 4; nt++)
                    mma_tf32(acc[mt][nt], aF[1][mt], bF[0][nt]);
#pragma unroll
            for (int mt = 0; mt < 4; mt++)
#pragma unroll
                for (int nt = 0; nt < 4; nt++)
                    mma_tf32(acc[mt][nt], aF[0][mt], bF[1][nt]);
        }
    };

    const int nsteps = K / 32;
    ldg(0);
    sts(0);
    __syncthreads();
    for (int step = 0; step < nsteps; step++) {
        const int s = step & 1;
        if (step + 1 < nsteps) ldg(step + 1);
        compute(s);
        if (step + 1 < nsteps) sts(1 - s);
        __syncthreads();
    }

    // epilogue
#pragma unroll
    for (int mt = 0; mt < 4; mt++) {
        const long long row = (long long)blockIdx.y * 128 + warp_m * 64 + mt * 16 + g;
        const long long col0 = (long long)blockIdx.x * 128 + warp_n * 32;
#pragma unroll
        for (int nt = 0; nt < 4; nt++) {
            const long long col = col0 + nt * 8 + t4 * 2;
            float2 v0 = make_float2(acc[mt][nt][0] * alpha, acc[mt][nt][1] * alpha);
            float2 v1 = make_float2(acc[mt][nt][2] * alpha, acc[mt][nt][3] * alpha);
            *reinterpret_cast<float2*>(Cg + row * ldC + col) = v0;
            *reinterpret_cast<float2*>(Cg + (row + 8) * ldC + col) = v1;
        }
    }
}

// ---------------- row softmax over S=2048 ----------------
__global__ __launch_bounds__(256) void softmax_kernel()
{
    const long long row = blockIdx.x;
    float* p = &g_scores[0] + row * (long long)S;
    const int t = threadIdx.x;

    float v[8];
    float m = -1e30f;
#pragma unroll
    for (int i = 0; i < 8; i++) {
        v[i] = p[t + i * 256];
        m = fmaxf(m, v[i]);
    }
    __shared__ float red[8];
#pragma unroll
    for (int o = 16; o; o >>= 1) m = fmaxf(m, __shfl_xor_sync(0xffffffffu, m, o));
    if ((t & 31) == 0) red[t >> 5] = m;
    __syncthreads();
    float mx = red[0];
#pragma unroll
    for (int w = 1; w < 8; w++) mx = fmaxf(mx, red[w]);

    float s = 0.f;
#pragma unroll
    for (int i = 0; i < 8; i++) {
        v[i] = __expf(v[i] - mx);
        s += v[i];
    }
#pragma unroll
    for (int o = 16; o; o >>= 1) s += __shfl_xor_sync(0xffffffffu, s, o);
    __syncthreads();
    if ((t & 31) == 0) red[t >> 5] = s;
    __syncthreads();
    float tot = 0.f;
#pragma unroll
    for (int w = 0; w < 8; w++) tot += red[w];
    const float inv = 1.0f / tot;
#pragma unroll
    for (int i = 0; i < 8; i++) p[t + i * 256] = v[i] * inv;
}

// ---------------- launch ----------------
extern "C" void kernel_launch(void* const* d_in, const int* in_sizes, int n_in,
                              void* d_out, int out_size)
{
    (void)in_sizes; (void)n_in; (void)out_size;
    const float* query = (const float*)d_in[0];
    const float* key   = (const float*)d_in[1];
    const float* value = (const float*)d_in[2];
    const float* Qw    = (const float*)d_in[3];
    const float* Kw    = (const float*)d_in[4];
    const float* Vw    = (const float*)d_in[5];
    const float* Qa    = (const float*)d_in[6];
    const float* Qb    = (const float*)d_in[7];
    const float* Ka    = (const float*)d_in[8];
    const float* Kb    = (const float*)d_in[9];
    const float* Va    = (const float*)d_in[10];
    const float* Vb    = (const float*)d_in[11];
    const float* Ow    = (const float*)d_in[12];
    float* out = (float*)d_out;

    static bool attr_done = false;
    if (!attr_done) {
        cudaFuncSetAttribute(gemm_hmma, cudaFuncAttributeMaxDynamicSharedMemorySize,
                             GEMM_SMEM_BYTES);
        attr_done = true;
    }

    const long long EE  = (long long)E * E;
    const long long BSE = (long long)BATCH * S * E;
    const long long SE  = (long long)S * E;
    const long long SS  = (long long)S * S;

    // 1. fold LoRA into weights
    weff_kernel<<<dim3(E * E / 256, 1, 3), 256>>>(Qw, Kw, Vw, Qa, Qb, Ka, Kb, Va, Vb);

    // 2. Q/K/V projections: [8192,1024] = X @ Weff^T
    const float* xs[3] = { query, key, value };
    for (int p = 0; p < 3; p++) {
        gemm_hmma<<<dim3(E / 128, BS / 128, 1), 256, GEMM_SMEM_BYTES>>>(
            xs[p],   SEL_EXT,  0,       E, 0,
            nullptr, SEL_WEFF, p * EE,  E, 0,
            nullptr, SEL_QKV,  p * BSE, E, 0,
            E, 1.0f);
    }

    // 3. transpose V -> Vt[b][e][s]
    transpose_v_kernel<<<dim3(S / 32, E / 32, BATCH), 256>>>();

    // 4. scores = Q @ K^T / 32
    gemm_hmma<<<dim3(S / 128, S / 128, BATCH), 256, GEMM_SMEM_BYTES>>>(
        nullptr, SEL_QKV,   0,   E, SE,
        nullptr, SEL_QKV,   BSE, E, SE,
        nullptr, SEL_SCORE, 0,   S, SS,
        E, 1.0f / 32.0f);

    // 5. softmax rows
    softmax_kernel<<<BATCH * S, 256>>>();

    // 6. attn_out = P @ Vt^T   (NT with Vt as [E,S] K-major)
    gemm_hmma<<<dim3(E / 128, S / 128, BATCH), 256, GEMM_SMEM_BYTES>>>(
        nullptr, SEL_SCORE, 0, S, SS,
        nullptr, SEL_VT,    0, S, SE,
        nullptr, SEL_AOUT,  0, E, SE,
        S, 1.0f);

    // 7. final = attn_out @ O^T
    gemm_hmma<<<dim3(E / 128, BS / 128, 1), 256, GEMM_SMEM_BYTES>>>(
        nullptr, SEL_AOUT, 0, E, 0,
        Ow,      SEL_EXT,  0, E, 0,
        out,     SEL_EXT,  0, E, 0,
        E, 1.0f);
}